// round 16
// baseline (speedup 1.0000x reference)
#include <cuda_runtime.h>
#include <cstdint>

typedef unsigned long long ull;

// ---------------- problem constants ----------------
constexpr int B = 64;
constexpr int N = 512;
constexpr int R = B * N;      // 32768 rows

// ---------------- device scratch ----------------
__device__ float g_WhT[(size_t)4 * R * 128];
__device__ float g_heads[(size_t)R * 384];
__device__ float g_x[(size_t)R * 128];
__device__ float g_src3[4 * R];
__device__ float g_dst3[4 * R];
__device__ uint32_t g_adjmask[(size_t)R * 128];
__device__ float g_WoutT[128 * 384];
__device__ float g_WcT[256 * 128];

__device__ __forceinline__ float lrelu02(float x) { return x > 0.f ? x : 0.2f * x; }
__device__ __forceinline__ float elu1(float x)    { return x > 0.f ? x : expm1f(x); }

__device__ __forceinline__ void fma2(ull& d, ull a, ull b) {
    asm("fma.rn.f32x2 %0, %1, %2, %3;" : "=l"(d) : "l"(a), "l"(b), "l"(d));
}
__device__ __forceinline__ ull pack2(float x) {
    ull r; asm("mov.b64 %0, {%1, %1};" : "=l"(r) : "f"(x)); return r;
}
__device__ __forceinline__ void unpack2(ull v, float& lo, float& hi) {
    asm("mov.b64 {%0, %1}, %2;" : "=f"(lo), "=f"(hi) : "l"(v));
}
__device__ __forceinline__ float totf32(float x) {
    float r; asm("cvt.rna.tf32.f32 %0, %1;" : "=f"(r) : "f"(x)); return r;
}
__device__ __forceinline__ uint32_t smem_u32(const void* p) {
    uint32_t a;
    asm("{ .reg .u64 t; cvta.to.shared.u64 t, %1; cvt.u32.u64 %0, t; }" : "=r"(a) : "l"(p));
    return a;
}
__device__ __forceinline__ void cp16(uint32_t dst, const void* src) {
    asm volatile("cp.async.cg.shared.global [%0], [%1], 16;" :: "r"(dst), "l"(src));
}
#define CP_COMMIT() asm volatile("cp.async.commit_group;" ::: "memory")
#define CP_WAIT0()  asm volatile("cp.async.wait_group 0;" ::: "memory")

__device__ __forceinline__ float mask_trunc(float p, uint32_t u) {
    return __uint_as_float(__float_as_uint(p) & u & 0xffffe000u);
}
__device__ __forceinline__ int swz4(int row, int c4) {
    return ((c4 ^ (row & 7)) << 2);
}

union F4U { float4 f; ull u[2]; };

__device__ __forceinline__ void mma_tf32(float* d,
    uint32_t a0, uint32_t a1, uint32_t a2, uint32_t a3,
    uint32_t b0, uint32_t b1)
{
    asm volatile(
        "mma.sync.aligned.m16n8k8.row.col.f32.tf32.tf32.f32 "
        "{%0,%1,%2,%3}, {%4,%5,%6,%7}, {%8,%9}, {%0,%1,%2,%3};"
        : "+f"(d[0]), "+f"(d[1]), "+f"(d[2]), "+f"(d[3])
        : "r"(a0), "r"(a1), "r"(a2), "r"(a3), "r"(b0), "r"(b1));
}

// ============ K_FRONT: fused proj34 (compute) + prepT + pack (HBM) ============
constexpr int PROJ_BLOCKS = 1536;
constexpr int PREP_BLOCKS = 320;
constexpr int PACK_BLOCKS = (R * 128) / 256;
constexpr int FRONT_BLOCKS = PROJ_BLOCKS + PREP_BLOCKS + PACK_BLOCKS;

__global__ __launch_bounds__(256) void k_front(
    const float* __restrict__ compound, const int* __restrict__ adj,
    const float* __restrict__ Wst, const float* __restrict__ ast,
    const float* __restrict__ Wout, const float* __restrict__ Wc,
    float* __restrict__ WhTout, float* __restrict__ srcout, float* __restrict__ dstout,
    float* __restrict__ WoutT, float* __restrict__ WcT,
    uint32_t* __restrict__ amask)
{
    __shared__ __align__(16) float WtS[34][128];
    __shared__ __align__(16) float htT[34][68];
    __shared__ float aS[256];

    const int bid = blockIdx.x;
    const int tid = threadIdx.x;

    if (bid >= PROJ_BLOCKS + PREP_BLOCKS) {
        int gid = (bid - PROJ_BLOCKS - PREP_BLOCKS) * 256 + tid;
        int4 v = reinterpret_cast<const int4*>(adj)[gid];
        uint32_t m = (v.x > 0 ? 0x000000FFu : 0u)
                   | (v.y > 0 ? 0x0000FF00u : 0u)
                   | (v.z > 0 ? 0x00FF0000u : 0u)
                   | (v.w > 0 ? 0xFF000000u : 0u);
        amask[gid] = m;
        return;
    }
    if (bid >= PROJ_BLOCKS) {
        int idx = (bid - PROJ_BLOCKS) * 256 + tid;
        if (idx < 128 * 384) {
            int f = idx / 384, k = idx % 384;
            WoutT[idx] = totf32(Wout[(size_t)k * 128 + f]);
        } else {
            int j = idx - 128 * 384;
            int c = j / 128, k = j % 128;
            WcT[j] = totf32(Wc[(size_t)k * 256 + c]);
        }
        return;
    }

    // ---- proj34 ----
    const int l   = bid / 512;
    const int rem = bid - l * 512;
    const int by  = rem >> 3;
    const int bx  = rem & 7;
    const float* W = Wst + (size_t)l * 34 * 128;
    const float* a = ast + l * 256;
    float* srcp = srcout + (size_t)l * R;
    float* dstp = dstout + (size_t)l * R;

    const int r0 = by * 512 + bx * 64;
    const int fg = tid & 31;
    const int ig = tid >> 5;

    aS[tid] = a[tid];

    for (int e = tid; e < 34 * 32; e += 256) {
        int k = e >> 5, c = e & 31;
        *reinterpret_cast<float4*>(&WtS[k][c * 4]) =
            *reinterpret_cast<const float4*>(&W[(size_t)k * 128 + c * 4]);
    }
    for (int e = tid; e < 64 * 34; e += 256) {
        int ii = e / 34, k = e - ii * 34;
        htT[k][ii] = compound[(size_t)(r0 + ii) * 34 + k];
    }
    __syncthreads();

    ull acc2[4][4];
#pragma unroll
    for (int rp = 0; rp < 4; ++rp)
#pragma unroll
        for (int c = 0; c < 4; ++c) acc2[rp][c] = 0ull;

#pragma unroll 8
    for (int k = 0; k < 34; ++k) {
        float4 w = *reinterpret_cast<const float4*>(&WtS[k][fg * 4]);
        ull w0 = pack2(w.x), w1 = pack2(w.y), w2 = pack2(w.z), w3 = pack2(w.w);
        F4U p0, p1;
        p0.f = *reinterpret_cast<const float4*>(&htT[k][ig * 8]);
        p1.f = *reinterpret_cast<const float4*>(&htT[k][ig * 8 + 4]);
        ull pr[4] = {p0.u[0], p0.u[1], p1.u[0], p1.u[1]};
#pragma unroll
        for (int rp = 0; rp < 4; ++rp) {
            fma2(acc2[rp][0], pr[rp], w0);
            fma2(acc2[rp][1], pr[rp], w1);
            fma2(acc2[rp][2], pr[rp], w2);
            fma2(acc2[rp][3], pr[rp], w3);
        }
    }

    float val[8][4];
#pragma unroll
    for (int rp = 0; rp < 4; ++rp)
#pragma unroll
        for (int c = 0; c < 4; ++c)
            unpack2(acc2[rp][c], val[2 * rp][c], val[2 * rp + 1][c]);

    {
        float* WT = WhTout + (size_t)l * R * 128 + (size_t)by * 128 * 512;
        const int il0 = bx * 64 + ig * 8;
#pragma unroll
        for (int c = 0; c < 4; ++c) {
            int f = fg * 4 + c;
            float4 lo = make_float4(totf32(val[0][c]), totf32(val[1][c]),
                                    totf32(val[2][c]), totf32(val[3][c]));
            float4 hi = make_float4(totf32(val[4][c]), totf32(val[5][c]),
                                    totf32(val[6][c]), totf32(val[7][c]));
            *reinterpret_cast<float4*>(&WT[(size_t)f * 512 + il0])     = lo;
            *reinterpret_cast<float4*>(&WT[(size_t)f * 512 + il0 + 4]) = hi;
        }
    }

    float a1v[4], a2v[4];
#pragma unroll
    for (int c = 0; c < 4; ++c) { a1v[c] = aS[fg * 4 + c]; a2v[c] = aS[128 + fg * 4 + c]; }

#pragma unroll
    for (int rr = 0; rr < 8; ++rr) {
        int i = r0 + ig * 8 + rr;
        float v1 = val[rr][0] * a1v[0] + val[rr][1] * a1v[1] + val[rr][2] * a1v[2] + val[rr][3] * a1v[3];
        float v2 = val[rr][0] * a2v[0] + val[rr][1] * a2v[1] + val[rr][2] * a2v[2] + val[rr][3] * a2v[3];
#pragma unroll
        for (int o2 = 16; o2; o2 >>= 1) {
            v1 += __shfl_xor_sync(0xffffffffu, v1, o2);
            v2 += __shfl_xor_sync(0xffffffffu, v2, o2);
        }
        if (fg == 0) { srcp[i] = v1; dstp[i] = v2; }
    }
}

// ============ K2: 128-row / 256-thread pipelined mma.sync tf32 GEMM (R14 version) ============
constexpr int TILE_F = 128 * 32;
constexpr int GEMM_SMEM_BYTES = 128 * 132 * 4;

template<int K, int LDX, int EPI>
__global__ __launch_bounds__(256, 2) void k_mma(
    const float* __restrict__ X, const float* __restrict__ WT,
    const float* __restrict__ vec,
    float* __restrict__ O,
    float* __restrict__ srcp, float* __restrict__ dstp)
{
    extern __shared__ __align__(16) float dyn[];
    float* XS = dyn;
    float* WS = dyn + 2 * TILE_F;
    __shared__ float vS[256];
    __shared__ float2 sred[128][2];

    const uint32_t xs_base = smem_u32(XS);
    const uint32_t ws_base = smem_u32(WS);

    const int r0   = blockIdx.x * 128;
    const int col0 = blockIdx.y * 128;
    const int tid  = threadIdx.x;
    const int w    = tid >> 5;
    const int lane = tid & 31;

    const float* WTb = WT + (size_t)col0 * K;

    if (EPI == 0) vS[tid] = vec[tid];
    else if (tid < 128) vS[tid] = vec[col0 + tid];

    const int wm = w & 3;
    const int wn = w >> 2;
    const int g  = lane >> 2;
    const int q  = lane & 3;

    const int sr = tid >> 3, c4 = tid & 7;

    float dacc[2][8][4];
#pragma unroll
    for (int mf = 0; mf < 2; ++mf)
#pragma unroll
        for (int nf = 0; nf < 8; ++nf)
#pragma unroll
            for (int c = 0; c < 4; ++c) dacc[mf][nf][c] = 0.f;

#pragma unroll
    for (int k = 0; k < 4; ++k) {
        int row = sr + k * 32;
        int so = row * 32 + swz4(row, c4);
        cp16(xs_base + (uint32_t)so * 4, X + (size_t)(r0 + row) * LDX + c4 * 4);
        cp16(ws_base + (uint32_t)so * 4, WTb + (size_t)row * K + c4 * 4);
    }
    CP_COMMIT();
    CP_WAIT0();
    __syncthreads();

    constexpr int NT = K / 32;
#pragma unroll 1
    for (int t = 0; t < NT; ++t) {
        const int cur = t & 1, nxt = cur ^ 1;
        if (t < NT - 1) {
            const int tj1 = (t + 1) * 32;
#pragma unroll
            for (int k = 0; k < 4; ++k) {
                int row = sr + k * 32;
                int so = row * 32 + swz4(row, c4);
                cp16(xs_base + (uint32_t)(nxt * TILE_F + so) * 4,
                     X + (size_t)(r0 + row) * LDX + tj1 + c4 * 4);
                cp16(ws_base + (uint32_t)(nxt * TILE_F + so) * 4,
                     WTb + (size_t)row * K + tj1 + c4 * 4);
            }
            CP_COMMIT();
        }

        const uint32_t* XSu = reinterpret_cast<const uint32_t*>(XS + cur * TILE_F);
        const uint32_t* WSu = reinterpret_cast<const uint32_t*>(WS + cur * TILE_F);
#pragma unroll
        for (int kk = 0; kk < 32; kk += 8) {
            const int k4a = kk >> 2, k4b = (kk >> 2) + 1;
            uint32_t bf0[8], bf1[8];
#pragma unroll
            for (int nf = 0; nf < 8; ++nf) {
                int f = wn * 64 + nf * 8 + g;
                bf0[nf] = WSu[f * 32 + ((k4a ^ g) << 2) + q];
                bf1[nf] = WSu[f * 32 + ((k4b ^ g) << 2) + q];
            }
#pragma unroll
            for (int mf = 0; mf < 2; ++mf) {
                int r_ = wm * 32 + mf * 16 + g;
                uint32_t a0 = XSu[r_ * 32 + ((k4a ^ g) << 2) + q];
                uint32_t a1 = XSu[(r_ + 8) * 32 + ((k4a ^ g) << 2) + q];
                uint32_t a2 = XSu[r_ * 32 + ((k4b ^ g) << 2) + q];
                uint32_t a3 = XSu[(r_ + 8) * 32 + ((k4b ^ g) << 2) + q];
#pragma unroll
                for (int nf = 0; nf < 8; ++nf)
                    mma_tf32(dacc[mf][nf], a0, a1, a2, a3, bf0[nf], bf1[nf]);
            }
        }

        if (t < NT - 1) CP_WAIT0();
        __syncthreads();
    }

    if (EPI == 1) {
#pragma unroll
        for (int mf = 0; mf < 2; ++mf) {
#pragma unroll
            for (int h = 0; h < 2; ++h) {
                int rl = wm * 32 + mf * 16 + g + h * 8;
                float* orow = O + (size_t)(r0 + rl) * 256 + col0 + wn * 64;
#pragma unroll
                for (int nf = 0; nf < 8; ++nf) {
                    int c0 = nf * 8 + 2 * q;
                    float2 v;
                    v.x = lrelu02(dacc[mf][nf][2 * h]     + vS[wn * 64 + c0]);
                    v.y = lrelu02(dacc[mf][nf][2 * h + 1] + vS[wn * 64 + c0 + 1]);
                    *reinterpret_cast<float2*>(&orow[c0]) = v;
                }
            }
        }
        return;
    }

    // EPI 0: fused src/dst + transposed WhT store
#pragma unroll
    for (int mf = 0; mf < 2; ++mf) {
#pragma unroll
        for (int h = 0; h < 2; ++h) {
            int rl = wm * 32 + mf * 16 + g + h * 8;
            float s1 = 0.f, s2 = 0.f;
#pragma unroll
            for (int nf = 0; nf < 8; ++nf) {
                int c0 = wn * 64 + nf * 8 + 2 * q;
                float v0 = dacc[mf][nf][2 * h], v1 = dacc[mf][nf][2 * h + 1];
                s1 += v0 * vS[c0] + v1 * vS[c0 + 1];
                s2 += v0 * vS[128 + c0] + v1 * vS[128 + c0 + 1];
            }
            s1 += __shfl_xor_sync(0xffffffffu, s1, 1);
            s1 += __shfl_xor_sync(0xffffffffu, s1, 2);
            s2 += __shfl_xor_sync(0xffffffffu, s2, 1);
            s2 += __shfl_xor_sync(0xffffffffu, s2, 2);
            if (q == 0) sred[rl][wn] = make_float2(s1, s2);
        }
    }
    __syncthreads();
    if (tid < 128) {
        float2 u = sred[tid][0], v = sred[tid][1];
        srcp[r0 + tid] = u.x + v.x;
        dstp[r0 + tid] = u.y + v.y;
    }

    float* WhS = dyn;   // 128 x 132
#pragma unroll
    for (int mf = 0; mf < 2; ++mf) {
#pragma unroll
        for (int h = 0; h < 2; ++h) {
            int rl = wm * 32 + mf * 16 + g + h * 8;
#pragma unroll
            for (int nf = 0; nf < 8; ++nf) {
                int c0 = wn * 64 + nf * 8 + 2 * q;
                *reinterpret_cast<float2*>(&WhS[rl * 132 + c0]) =
                    make_float2(dacc[mf][nf][2 * h], dacc[mf][nf][2 * h + 1]);
            }
        }
    }
    __syncthreads();
    {
        const int f = tid >> 1, ih = tid & 1;
        float* WTo = O + (size_t)(r0 >> 9) * (128 * 512)
                       + (size_t)f * 512 + (r0 & 511) + ih * 64;
#pragma unroll
        for (int v = 0; v < 16; ++v) {
            int i = ih * 64 + v * 4;
            float4 o = make_float4(totf32(WhS[(i + 0) * 132 + f]),
                                   totf32(WhS[(i + 1) * 132 + f]),
                                   totf32(WhS[(i + 2) * 132 + f]),
                                   totf32(WhS[(i + 3) * 132 + f]));
            *reinterpret_cast<float4*>(&WTo[v * 4]) = o;
        }
    }
}

// ============ K3: 64-row pipelined mma.sync tf32 fused softmax + aggregate (R14) ============
constexpr int WT_F  = 128 * 32;
constexpr int PS_F  = 64 * 32;
constexpr int WS_OFF  = 0;
constexpr int PS_OFF  = WS_OFF + 2 * WT_F;
constexpr int DST_OFF = PS_OFF + 2 * PS_F;
constexpr int FS_OFF  = DST_OFF + 512;
constexpr int SRC_OFF = FS_OFF + 1024;
constexpr int E1_OFF  = SRC_OFF + 64;
constexpr int E2_OFF  = E1_OFF + 64;
constexpr int RZ_OFF  = E2_OFF + 64;
constexpr int RED_OFF = RZ_OFF + 64;
constexpr int MD_OFF  = RED_OFF + 4;
constexpr int AGG_SMEM_BYTES = (MD_OFF + 4) * 4;

__global__ __launch_bounds__(128, 4) void k_agg_mma(
    const uint32_t* __restrict__ amask, const float* __restrict__ WhT0,
    const float* __restrict__ src0, const float* __restrict__ dst0,
    float* __restrict__ outp, int ld)
{
    extern __shared__ __align__(16) float dyn[];
    float* WSf  = dyn + WS_OFF;
    float* PSf  = dyn + PS_OFF;
    float* dstS = dyn + DST_OFF;
    float2* FS2 = reinterpret_cast<float2*>(dyn + FS_OFF);
    float* srcS = dyn + SRC_OFF;
    float* e1S  = dyn + E1_OFF;
    float* e2S  = dyn + E2_OFF;
    float* rZS  = dyn + RZ_OFF;
    float* red  = dyn + RED_OFF;
    float* mdstS = dyn + MD_OFF;

    const uint32_t ws_base = smem_u32(WSf);

    const int l    = blockIdx.z;
    const int b    = blockIdx.y;
    const int i0   = blockIdx.x * 64;
    const int tid  = threadIdx.x;
    const int w    = tid >> 5;
    const int lane = tid & 31;
    const int col0 = l * 128;

    const float* WhTl = WhT0 + (size_t)l * R * 128 + (size_t)b * 128 * 512;
    const float* srcp = src0 + (size_t)l * R;
    const float* dstp = dst0 + (size_t)l * R;
    const uint32_t* maskb = amask + ((size_t)(b << 9) + i0) * 128;

    for (int k = tid; k < 512; k += 128) dstS[k] = dstp[(b << 9) + k];
    if (tid < 64) srcS[tid] = srcp[(b << 9) + i0 + tid];
    __syncthreads();

    {
        float v = fmaxf(fmaxf(dstS[tid], dstS[tid + 128]),
                        fmaxf(dstS[tid + 256], dstS[tid + 384]));
#pragma unroll
        for (int o = 16; o; o >>= 1) v = fmaxf(v, __shfl_xor_sync(0xffffffffu, v, o));
        if (lane == 0) red[w] = v;
        __syncthreads();
        if (tid == 0) {
            float m = fmaxf(fmaxf(red[0], red[1]), fmaxf(red[2], red[3]));
            mdstS[0] = m;
        }
        __syncthreads();
    }
    const float mdst = mdstS[0];

    for (int k = tid; k < 512; k += 128) {
        float d = dstS[k] - mdst;
        FS2[k] = make_float2(__expf(d), __expf(0.2f * d));
    }
    if (tid < 64) {
        float t2 = srcS[tid] + mdst;
        float m  = fmaxf(t2, 0.2f * t2);
        e1S[tid] = __expf(t2 - m);
        e2S[tid] = __expf(0.2f * t2 - m);
    }
    __syncthreads();

    const int wm = w & 1;
    const int wn = w >> 1;
    const int g  = lane >> 2;
    const int q  = lane & 3;

    const int srow = tid >> 3;
    const int jq   = tid & 7;

    float E1r[4], E2r[4];
#pragma unroll
    for (int qq = 0; qq < 4; ++qq) {
        E1r[qq] = e1S[srow + qq * 16];
        E2r[qq] = e2S[srow + qq * 16];
    }

    float dacc[2][8][4];
#pragma unroll
    for (int mf = 0; mf < 2; ++mf)
#pragma unroll
        for (int nf = 0; nf < 8; ++nf)
#pragma unroll
            for (int c = 0; c < 4; ++c) dacc[mf][nf][c] = 0.f;

    float zl[4] = {0.f, 0.f, 0.f, 0.f};

#pragma unroll
    for (int k = 0; k < 8; ++k) {
        int row = srow + k * 16;
        int so = row * 32 + swz4(row, jq);
        cp16(ws_base + (uint32_t)so * 4, WhTl + (size_t)row * 512 + jq * 4);
    }
    CP_COMMIT();
    {
        const float4* fsp = reinterpret_cast<const float4*>(&FS2[jq * 4]);
        float4 f01 = fsp[0], f23 = fsp[1];
#pragma unroll
        for (int qq = 0; qq < 4; ++qq) {
            int r_ = srow + qq * 16;
            uint32_t mw = maskb[r_ * 128 + jq];
            float E1 = E1r[qq], E2 = E2r[qq];
            float p0 = mask_trunc(fmaxf(E1 * f01.x, E2 * f01.y), __byte_perm(mw, 0, 0x0000));
            float p1 = mask_trunc(fmaxf(E1 * f01.z, E2 * f01.w), __byte_perm(mw, 0, 0x1111));
            float p2 = mask_trunc(fmaxf(E1 * f23.x, E2 * f23.y), __byte_perm(mw, 0, 0x2222));
            float p3 = mask_trunc(fmaxf(E1 * f23.z, E2 * f23.w), __byte_perm(mw, 0, 0x3333));
            zl[qq] += (p0 + p1) + (p2 + p3);
            *reinterpret_cast<float4*>(&PSf[r_ * 32 + swz4(r_, jq)]) =
                make_float4(p0, p1, p2, p3);
        }
    }
    CP_WAIT0();
    __syncthreads();

#pragma unroll 1
    for (int t = 0; t < 16; ++t) {
        const int cur = t & 1, nxt = cur ^ 1;

        if (t < 15) {
            const int tj1 = (t + 1) * 32;
#pragma unroll
            for (int k = 0; k < 8; ++k) {
                int row = srow + k * 16;
                int so = row * 32 + swz4(row, jq);
                cp16(ws_base + (uint32_t)(nxt * WT_F + so) * 4,
                     WhTl + (size_t)row * 512 + tj1 + jq * 4);
            }
            CP_COMMIT();

            const float4* fsp = reinterpret_cast<const float4*>(&FS2[tj1 + jq * 4]);
            float4 f01 = fsp[0], f23 = fsp[1];
            float* PSb = PSf + nxt * PS_F;
            const int wofs = (t + 1) * 8 + jq;
#pragma unroll
            for (int qq = 0; qq < 4; ++qq) {
                int r_ = srow + qq * 16;
                uint32_t mw = maskb[r_ * 128 + wofs];
                float E1 = E1r[qq], E2 = E2r[qq];
                float p0 = mask_trunc(fmaxf(E1 * f01.x, E2 * f01.y), __byte_perm(mw, 0, 0x0000));
                float p1 = mask_trunc(fmaxf(E1 * f01.z, E2 * f01.w), __byte_perm(mw, 0, 0x1111));
                float p2 = mask_trunc(fmaxf(E1 * f23.x, E2 * f23.y), __byte_perm(mw, 0, 0x2222));
                float p3 = mask_trunc(fmaxf(E1 * f23.z, E2 * f23.w), __byte_perm(mw, 0, 0x3333));
                zl[qq] += (p0 + p1) + (p2 + p3);
                *reinterpret_cast<float4*>(&PSb[r_ * 32 + swz4(r_, jq)]) =
                    make_float4(p0, p1, p2, p3);
            }
        }

        const uint32_t* PSu = reinterpret_cast<const uint32_t*>(PSf + cur * PS_F);
        const uint32_t* WSu = reinterpret_cast<const uint32_t*>(WSf + cur * WT_F);
#pragma unroll
        for (int kk = 0; kk < 32; kk += 8) {
            const int k4a = kk >> 2, k4b = (kk >> 2) + 1;
            uint32_t bf0[8], bf1[8];
#pragma unroll
            for (int nf = 0; nf < 8; ++nf) {
                int f = wn * 64 + nf * 8 + g;
                bf0[nf] = WSu[f * 32 + ((k4a ^ g) << 2) + q];
                bf1[nf] = WSu[f * 32 + ((k4b ^ g) << 2) + q];
            }
#pragma unroll
            for (int mf = 0; mf < 2; ++mf) {
                int r_ = wm * 32 + mf * 16 + g;
                uint32_t a0 = PSu[r_ * 32 + ((k4a ^ g) << 2) + q];
                uint32_t a1 = PSu[(r_ + 8) * 32 + ((k4a ^ g) << 2) + q];
                uint32_t a2 = PSu[r_ * 32 + ((k4b ^ g) << 2) + q];
                uint32_t a3 = PSu[(r_ + 8) * 32 + ((k4b ^ g) << 2) + q];
#pragma unroll
                for (int nf = 0; nf < 8; ++nf)
                    mma_tf32(dacc[mf][nf], a0, a1, a2, a3, bf0[nf], bf1[nf]);
            }
        }

        if (t < 15) CP_WAIT0();
        __syncthreads();
    }

    float* zpartS = dyn + WS_OFF;
#pragma unroll
    for (int qq = 0; qq < 4; ++qq) zpartS[(srow + qq * 16) * 8 + jq] = zl[qq];
    __syncthreads();
    if (tid < 64) {
        float z = 0.f;
#pragma unroll
        for (int k = 0; k < 8; ++k) z += zpartS[tid * 8 + k];
        rZS[tid] = 1.f / z;
    }
    __syncthreads();

#pragma unroll
    for (int mf = 0; mf < 2; ++mf) {
#pragma unroll
        for (int h = 0; h < 2; ++h) {
            int rl = wm * 32 + mf * 16 + g + h * 8;
            float rz = rZS[rl];
            float* orow = outp + ((size_t)(b << 9) + i0 + rl) * ld + col0 + wn * 64;
#pragma unroll
            for (int nf = 0; nf < 8; ++nf) {
                float2 v;
                v.x = totf32(elu1(dacc[mf][nf][2 * h]     * rz));
                v.y = totf32(elu1(dacc[mf][nf][2 * h + 1] * rz));
                *reinterpret_cast<float2*>(&orow[nf * 8 + 2 * q]) = v;
            }
        }
    }
}

// ---------------- launch ----------------
extern "C" void kernel_launch(void* const* d_in, const int* in_sizes, int n_in,
                              void* d_out, int out_size)
{
    (void)in_sizes; (void)n_in; (void)out_size;
    const float* compound = (const float*)d_in[0];
    const int*   adj      = (const int*)d_in[1];
    const float* Wst      = (const float*)d_in[2];
    const float* ast      = (const float*)d_in[3];
    const float* Wout     = (const float*)d_in[4];
    const float* aout     = (const float*)d_in[5];
    const float* Wc       = (const float*)d_in[6];
    const float* bc       = (const float*)d_in[7];
    float* out = (float*)d_out;

    float* g_WhT_p;   cudaGetSymbolAddress((void**)&g_WhT_p,  g_WhT);
    float* g_heads_p; cudaGetSymbolAddress((void**)&g_heads_p, g_heads);
    float* g_x_p;     cudaGetSymbolAddress((void**)&g_x_p,    g_x);
    float* g_src_p;   cudaGetSymbolAddress((void**)&g_src_p,  g_src3);
    float* g_dst_p;   cudaGetSymbolAddress((void**)&g_dst_p,  g_dst3);
    uint32_t* g_mask_p; cudaGetSymbolAddress((void**)&g_mask_p, g_adjmask);
    float* g_WoutT_p; cudaGetSymbolAddress((void**)&g_WoutT_p, g_WoutT);
    float* g_WcT_p;   cudaGetSymbolAddress((void**)&g_WcT_p,   g_WcT);

    cudaFuncSetAttribute(k_agg_mma, cudaFuncAttributeMaxDynamicSharedMemorySize,
                         AGG_SMEM_BYTES);
    cudaFuncSetAttribute(k_mma<384, 384, 0>,
                         cudaFuncAttributeMaxDynamicSharedMemorySize, GEMM_SMEM_BYTES);
    cudaFuncSetAttribute(k_mma<128, 128, 1>,
                         cudaFuncAttributeMaxDynamicSharedMemorySize, GEMM_SMEM_BYTES);

    // fused front: proj34 (compute) overlapped with pack/prepT (HBM)
    k_front<<<FRONT_BLOCKS, 256>>>(compound, adj, Wst, ast, Wout, Wc,
                                   g_WhT_p, g_src_p, g_dst_p,
                                   g_WoutT_p, g_WcT_p, g_mask_p);

    // 3 head aggregations (64-row CTAs, 4 CTAs/SM)
    k_agg_mma<<<dim3(N / 64, B, 3), 128, AGG_SMEM_BYTES>>>(
        g_mask_p, g_WhT_p, g_src_p, g_dst_p, g_heads_p, 384);

    // out-layer projection (128-row mma GEMM, fused src/dst + WhT store)
    k_mma<384, 384, 0><<<dim3(R / 128, 1), 256, GEMM_SMEM_BYTES>>>(
        g_heads_p, g_WoutT_p, aout,
        g_WhT_p + (size_t)3 * R * 128, g_src_p + (size_t)3 * R, g_dst_p + (size_t)3 * R);

    // out-layer aggregation
    k_agg_mma<<<dim3(N / 64, B, 1), 128, AGG_SMEM_BYTES>>>(
        g_mask_p, g_WhT_p + (size_t)3 * R * 128,
        g_src_p + (size_t)3 * R, g_dst_p + (size_t)3 * R, g_x_p, 128);

    // final dense layer (128-row mma GEMM)
    k_mma<128, 128, 1><<<dim3(R / 128, 2), 256, GEMM_SMEM_BYTES>>>(
        g_x_p, g_WcT_p, bc, out, nullptr, nullptr);
}

// round 17
// speedup vs baseline: 1.0308x; 1.0308x over previous
#include <cuda_runtime.h>
#include <cstdint>

typedef unsigned long long ull;

// ---------------- problem constants ----------------
constexpr int B = 64;
constexpr int N = 512;
constexpr int R = B * N;      // 32768 rows

// ---------------- device scratch ----------------
__device__ float g_WhT[(size_t)4 * R * 128];
__device__ float g_heads[(size_t)R * 384];
__device__ float g_x[(size_t)R * 128];
__device__ float g_src3[4 * R];
__device__ float g_dst3[4 * R];
__device__ uint32_t g_adjmask[(size_t)R * 128];
__device__ float g_WoutT[128 * 384];
__device__ float g_WcT[256 * 128];

__device__ __forceinline__ float lrelu02(float x) { return x > 0.f ? x : 0.2f * x; }
__device__ __forceinline__ float elu1(float x)    { return x > 0.f ? x : expm1f(x); }

__device__ __forceinline__ void fma2(ull& d, ull a, ull b) {
    asm("fma.rn.f32x2 %0, %1, %2, %3;" : "=l"(d) : "l"(a), "l"(b), "l"(d));
}
__device__ __forceinline__ ull pack2(float x) {
    ull r; asm("mov.b64 %0, {%1, %1};" : "=l"(r) : "f"(x)); return r;
}
__device__ __forceinline__ void unpack2(ull v, float& lo, float& hi) {
    asm("mov.b64 {%0, %1}, %2;" : "=f"(lo), "=f"(hi) : "l"(v));
}
__device__ __forceinline__ float totf32(float x) {
    float r; asm("cvt.rna.tf32.f32 %0, %1;" : "=f"(r) : "f"(x)); return r;
}
__device__ __forceinline__ uint32_t smem_u32(const void* p) {
    uint32_t a;
    asm("{ .reg .u64 t; cvta.to.shared.u64 t, %1; cvt.u32.u64 %0, t; }" : "=r"(a) : "l"(p));
    return a;
}
__device__ __forceinline__ void cp16(uint32_t dst, const void* src) {
    asm volatile("cp.async.cg.shared.global [%0], [%1], 16;" :: "r"(dst), "l"(src));
}
#define CP_COMMIT() asm volatile("cp.async.commit_group;" ::: "memory")
#define CP_WAIT0()  asm volatile("cp.async.wait_group 0;" ::: "memory")

__device__ __forceinline__ float mask_trunc(float p, uint32_t u) {
    return __uint_as_float(__float_as_uint(p) & u & 0xffffe000u);
}
__device__ __forceinline__ int swz4(int row, int c4) {
    return ((c4 ^ (row & 7)) << 2);
}

union F4U { float4 f; ull u[2]; };

__device__ __forceinline__ void mma_tf32(float* d,
    uint32_t a0, uint32_t a1, uint32_t a2, uint32_t a3,
    uint32_t b0, uint32_t b1)
{
    asm volatile(
        "mma.sync.aligned.m16n8k8.row.col.f32.tf32.tf32.f32 "
        "{%0,%1,%2,%3}, {%4,%5,%6,%7}, {%8,%9}, {%0,%1,%2,%3};"
        : "+f"(d[0]), "+f"(d[1]), "+f"(d[2]), "+f"(d[3])
        : "r"(a0), "r"(a1), "r"(a2), "r"(a3), "r"(b0), "r"(b1));
}

// ============ K0a: pack adj into byte masks (2 words per thread) ============
__global__ __launch_bounds__(256) void k_pack(const int* __restrict__ adj,
                                              uint32_t* __restrict__ mask)
{
    int gid = (blockIdx.x * 256 + threadIdx.x) * 2;
    const int4* p = reinterpret_cast<const int4*>(adj);
#pragma unroll
    for (int u = 0; u < 2; ++u) {
        int4 v = p[gid + u];
        uint32_t m = (v.x > 0 ? 0x000000FFu : 0u)
                   | (v.y > 0 ? 0x0000FF00u : 0u)
                   | (v.z > 0 ? 0x00FF0000u : 0u)
                   | (v.w > 0 ? 0xFF000000u : 0u);
        mask[gid + u] = m;
    }
}

// ============ K0b: transpose+round weights ============
__global__ __launch_bounds__(256) void k_prepT(const float* __restrict__ Wout,
                                               const float* __restrict__ Wc,
                                               float* __restrict__ WoutT,
                                               float* __restrict__ WcT)
{
    int idx = blockIdx.x * 256 + threadIdx.x;
    if (idx < 128 * 384) {
        int f = idx / 384, k = idx % 384;
        WoutT[idx] = totf32(Wout[(size_t)k * 128 + f]);
    } else {
        int j = idx - 128 * 384;
        if (j < 256 * 128) {
            int c = j / 128, k = j % 128;
            WcT[j] = totf32(Wc[(size_t)k * 256 + c]);
        }
    }
}

// ============ K1: blocked GEMM Wh = X @ W (fused src/dst); stores WhT tf32 ============
template<int FIN, int TK>
__global__ __launch_bounds__(256) void k_proj(
    const float* __restrict__ X, int ldx,
    const float* __restrict__ Wbase, const float* __restrict__ abase,
    float* __restrict__ WhTout, float* __restrict__ srcout, float* __restrict__ dstout)
{
    __shared__ __align__(16) float WtS[TK][128];
    __shared__ __align__(16) float htT[TK][68];
    __shared__ float aS[256];

    const int l   = blockIdx.z;
    const float* W = Wbase + (size_t)l * FIN * 128;
    const float* a = abase + l * 256;
    float* srcp = srcout + (size_t)l * R;
    float* dstp = dstout + (size_t)l * R;

    const int r0  = blockIdx.y * 512 + blockIdx.x * 64;
    const int tid = threadIdx.x;
    const int fg  = tid & 31;
    const int ig  = tid >> 5;

    aS[tid] = a[tid];

    ull acc2[4][4];
#pragma unroll
    for (int rp = 0; rp < 4; ++rp)
#pragma unroll
        for (int c = 0; c < 4; ++c) acc2[rp][c] = 0ull;

    for (int k0 = 0; k0 < FIN; k0 += TK) {
        __syncthreads();
        for (int e = tid; e < TK * 32; e += 256) {
            int k = e >> 5, c = e & 31;
            *reinterpret_cast<float4*>(&WtS[k][c * 4]) =
                *reinterpret_cast<const float4*>(&W[(size_t)(k0 + k) * 128 + c * 4]);
        }
        for (int e = tid; e < 64 * TK; e += 256) {
            int ii = e / TK, k = e - ii * TK;
            htT[k][ii] = X[(size_t)(r0 + ii) * ldx + k0 + k];
        }
        __syncthreads();

#pragma unroll 8
        for (int k = 0; k < TK; ++k) {
            float4 w = *reinterpret_cast<const float4*>(&WtS[k][fg * 4]);
            ull w0 = pack2(w.x), w1 = pack2(w.y), w2 = pack2(w.z), w3 = pack2(w.w);
            F4U p0, p1;
            p0.f = *reinterpret_cast<const float4*>(&htT[k][ig * 8]);
            p1.f = *reinterpret_cast<const float4*>(&htT[k][ig * 8 + 4]);
            ull pr[4] = {p0.u[0], p0.u[1], p1.u[0], p1.u[1]};
#pragma unroll
            for (int rp = 0; rp < 4; ++rp) {
                fma2(acc2[rp][0], pr[rp], w0);
                fma2(acc2[rp][1], pr[rp], w1);
                fma2(acc2[rp][2], pr[rp], w2);
                fma2(acc2[rp][3], pr[rp], w3);
            }
        }
    }

    float val[8][4];
#pragma unroll
    for (int rp = 0; rp < 4; ++rp)
#pragma unroll
        for (int c = 0; c < 4; ++c)
            unpack2(acc2[rp][c], val[2 * rp][c], val[2 * rp + 1][c]);

    {
        float* WT = WhTout + (size_t)l * R * 128 + (size_t)blockIdx.y * 128 * 512;
        const int il0 = blockIdx.x * 64 + ig * 8;
#pragma unroll
        for (int c = 0; c < 4; ++c) {
            int f = fg * 4 + c;
            float4 lo = make_float4(totf32(val[0][c]), totf32(val[1][c]),
                                    totf32(val[2][c]), totf32(val[3][c]));
            float4 hi = make_float4(totf32(val[4][c]), totf32(val[5][c]),
                                    totf32(val[6][c]), totf32(val[7][c]));
            *reinterpret_cast<float4*>(&WT[(size_t)f * 512 + il0])     = lo;
            *reinterpret_cast<float4*>(&WT[(size_t)f * 512 + il0 + 4]) = hi;
        }
    }

    float a1v[4], a2v[4];
#pragma unroll
    for (int c = 0; c < 4; ++c) { a1v[c] = aS[fg * 4 + c]; a2v[c] = aS[128 + fg * 4 + c]; }

#pragma unroll
    for (int rr = 0; rr < 8; ++rr) {
        int i = r0 + ig * 8 + rr;
        float v1 = val[rr][0] * a1v[0] + val[rr][1] * a1v[1] + val[rr][2] * a1v[2] + val[rr][3] * a1v[3];
        float v2 = val[rr][0] * a2v[0] + val[rr][1] * a2v[1] + val[rr][2] * a2v[2] + val[rr][3] * a2v[3];
#pragma unroll
        for (int o2 = 16; o2; o2 >>= 1) {
            v1 += __shfl_xor_sync(0xffffffffu, v1, o2);
            v2 += __shfl_xor_sync(0xffffffffu, v2, o2);
        }
        if (fg == 0) { srcp[i] = v1; dstp[i] = v2; }
    }
}

// ============ K2: 128-row / 256-thread pipelined mma.sync tf32 GEMM ============
constexpr int TILE_F = 128 * 32;
constexpr int GEMM_SMEM_BYTES = 128 * 132 * 4;

template<int K, int LDX, int EPI>
__global__ __launch_bounds__(256, 2) void k_mma(
    const float* __restrict__ X, const float* __restrict__ WT,
    const float* __restrict__ vec,
    float* __restrict__ O,
    float* __restrict__ srcp, float* __restrict__ dstp)
{
    extern __shared__ __align__(16) float dyn[];
    float* XS = dyn;
    float* WS = dyn + 2 * TILE_F;
    __shared__ float vS[256];
    __shared__ float2 sred[128][2];

    const uint32_t xs_base = smem_u32(XS);
    const uint32_t ws_base = smem_u32(WS);

    const int r0   = blockIdx.x * 128;
    const int col0 = blockIdx.y * 128;
    const int tid  = threadIdx.x;
    const int w    = tid >> 5;
    const int lane = tid & 31;

    const float* WTb = WT + (size_t)col0 * K;

    if (EPI == 0) vS[tid] = vec[tid];
    else if (tid < 128) vS[tid] = vec[col0 + tid];

    const int wm = w & 3;
    const int wn = w >> 2;
    const int g  = lane >> 2;
    const int q  = lane & 3;

    const int sr = tid >> 3, c4 = tid & 7;

    float dacc[2][8][4];
#pragma unroll
    for (int mf = 0; mf < 2; ++mf)
#pragma unroll
        for (int nf = 0; nf < 8; ++nf)
#pragma unroll
            for (int c = 0; c < 4; ++c) dacc[mf][nf][c] = 0.f;

#pragma unroll
    for (int k = 0; k < 4; ++k) {
        int row = sr + k * 32;
        int so = row * 32 + swz4(row, c4);
        cp16(xs_base + (uint32_t)so * 4, X + (size_t)(r0 + row) * LDX + c4 * 4);
        cp16(ws_base + (uint32_t)so * 4, WTb + (size_t)row * K + c4 * 4);
    }
    CP_COMMIT();
    CP_WAIT0();
    __syncthreads();

    constexpr int NT = K / 32;
#pragma unroll 1
    for (int t = 0; t < NT; ++t) {
        const int cur = t & 1, nxt = cur ^ 1;
        if (t < NT - 1) {
            const int tj1 = (t + 1) * 32;
#pragma unroll
            for (int k = 0; k < 4; ++k) {
                int row = sr + k * 32;
                int so = row * 32 + swz4(row, c4);
                cp16(xs_base + (uint32_t)(nxt * TILE_F + so) * 4,
                     X + (size_t)(r0 + row) * LDX + tj1 + c4 * 4);
                cp16(ws_base + (uint32_t)(nxt * TILE_F + so) * 4,
                     WTb + (size_t)row * K + tj1 + c4 * 4);
            }
            CP_COMMIT();
        }

        const uint32_t* XSu = reinterpret_cast<const uint32_t*>(XS + cur * TILE_F);
        const uint32_t* WSu = reinterpret_cast<const uint32_t*>(WS + cur * TILE_F);
#pragma unroll
        for (int kk = 0; kk < 32; kk += 8) {
            const int k4a = kk >> 2, k4b = (kk >> 2) + 1;
            uint32_t bf0[8], bf1[8];
#pragma unroll
            for (int nf = 0; nf < 8; ++nf) {
                int f = wn * 64 + nf * 8 + g;
                bf0[nf] = WSu[f * 32 + ((k4a ^ g) << 2) + q];
                bf1[nf] = WSu[f * 32 + ((k4b ^ g) << 2) + q];
            }
#pragma unroll
            for (int mf = 0; mf < 2; ++mf) {
                int r_ = wm * 32 + mf * 16 + g;
                uint32_t a0 = XSu[r_ * 32 + ((k4a ^ g) << 2) + q];
                uint32_t a1 = XSu[(r_ + 8) * 32 + ((k4a ^ g) << 2) + q];
                uint32_t a2 = XSu[r_ * 32 + ((k4b ^ g) << 2) + q];
                uint32_t a3 = XSu[(r_ + 8) * 32 + ((k4b ^ g) << 2) + q];
#pragma unroll
                for (int nf = 0; nf < 8; ++nf)
                    mma_tf32(dacc[mf][nf], a0, a1, a2, a3, bf0[nf], bf1[nf]);
            }
        }

        if (t < NT - 1) CP_WAIT0();
        __syncthreads();
    }

    if (EPI == 1) {
#pragma unroll
        for (int mf = 0; mf < 2; ++mf) {
#pragma unroll
            for (int h = 0; h < 2; ++h) {
                int rl = wm * 32 + mf * 16 + g + h * 8;
                float* orow = O + (size_t)(r0 + rl) * 256 + col0 + wn * 64;
#pragma unroll
                for (int nf = 0; nf < 8; ++nf) {
                    int c0 = nf * 8 + 2 * q;
                    float2 v;
                    v.x = lrelu02(dacc[mf][nf][2 * h]     + vS[wn * 64 + c0]);
                    v.y = lrelu02(dacc[mf][nf][2 * h + 1] + vS[wn * 64 + c0 + 1]);
                    *reinterpret_cast<float2*>(&orow[c0]) = v;
                }
            }
        }
        return;
    }

    // EPI 0: fused src/dst + transposed WhT store
#pragma unroll
    for (int mf = 0; mf < 2; ++mf) {
#pragma unroll
        for (int h = 0; h < 2; ++h) {
            int rl = wm * 32 + mf * 16 + g + h * 8;
            float s1 = 0.f, s2 = 0.f;
#pragma unroll
            for (int nf = 0; nf < 8; ++nf) {
                int c0 = wn * 64 + nf * 8 + 2 * q;
                float v0 = dacc[mf][nf][2 * h], v1 = dacc[mf][nf][2 * h + 1];
                s1 += v0 * vS[c0] + v1 * vS[c0 + 1];
                s2 += v0 * vS[128 + c0] + v1 * vS[128 + c0 + 1];
            }
            s1 += __shfl_xor_sync(0xffffffffu, s1, 1);
            s1 += __shfl_xor_sync(0xffffffffu, s1, 2);
            s2 += __shfl_xor_sync(0xffffffffu, s2, 1);
            s2 += __shfl_xor_sync(0xffffffffu, s2, 2);
            if (q == 0) sred[rl][wn] = make_float2(s1, s2);
        }
    }
    __syncthreads();
    if (tid < 128) {
        float2 u = sred[tid][0], v = sred[tid][1];
        srcp[r0 + tid] = u.x + v.x;
        dstp[r0 + tid] = u.y + v.y;
    }

    float* WhS = dyn;   // 128 x 132
#pragma unroll
    for (int mf = 0; mf < 2; ++mf) {
#pragma unroll
        for (int h = 0; h < 2; ++h) {
            int rl = wm * 32 + mf * 16 + g + h * 8;
#pragma unroll
            for (int nf = 0; nf < 8; ++nf) {
                int c0 = wn * 64 + nf * 8 + 2 * q;
                *reinterpret_cast<float2*>(&WhS[rl * 132 + c0]) =
                    make_float2(dacc[mf][nf][2 * h], dacc[mf][nf][2 * h + 1]);
            }
        }
    }
    __syncthreads();
    {
        const int f = tid >> 1, ih = tid & 1;
        float* WTo = O + (size_t)(r0 >> 9) * (128 * 512)
                       + (size_t)f * 512 + (r0 & 511) + ih * 64;
#pragma unroll
        for (int v = 0; v < 16; ++v) {
            int i = ih * 64 + v * 4;
            float4 o = make_float4(totf32(WhS[(i + 0) * 132 + f]),
                                   totf32(WhS[(i + 1) * 132 + f]),
                                   totf32(WhS[(i + 2) * 132 + f]),
                                   totf32(WhS[(i + 3) * 132 + f]));
            *reinterpret_cast<float4*>(&WTo[v * 4]) = o;
        }
    }
}

// ============ K3: 64-row pipelined mma.sync tf32 fused softmax + aggregate ============
constexpr int WT_F  = 128 * 32;
constexpr int PS_F  = 64 * 32;
constexpr int WS_OFF  = 0;
constexpr int PS_OFF  = WS_OFF + 2 * WT_F;
constexpr int DST_OFF = PS_OFF + 2 * PS_F;
constexpr int FS_OFF  = DST_OFF + 512;
constexpr int SRC_OFF = FS_OFF + 1024;
constexpr int E1_OFF  = SRC_OFF + 64;
constexpr int E2_OFF  = E1_OFF + 64;
constexpr int RZ_OFF  = E2_OFF + 64;
constexpr int RED_OFF = RZ_OFF + 64;
constexpr int MD_OFF  = RED_OFF + 4;
constexpr int AGG_SMEM_BYTES = (MD_OFF + 4) * 4;

__global__ __launch_bounds__(128, 4) void k_agg_mma(
    const uint32_t* __restrict__ amask, const float* __restrict__ WhT0,
    const float* __restrict__ src0, const float* __restrict__ dst0,
    float* __restrict__ outp, int ld)
{
    extern __shared__ __align__(16) float dyn[];
    float* WSf  = dyn + WS_OFF;
    float* PSf  = dyn + PS_OFF;
    float* dstS = dyn + DST_OFF;
    float2* FS2 = reinterpret_cast<float2*>(dyn + FS_OFF);
    float* srcS = dyn + SRC_OFF;
    float* e1S  = dyn + E1_OFF;
    float* e2S  = dyn + E2_OFF;
    float* rZS  = dyn + RZ_OFF;
    float* red  = dyn + RED_OFF;
    float* mdstS = dyn + MD_OFF;

    const uint32_t ws_base = smem_u32(WSf);

    const int l    = blockIdx.z;
    const int b    = blockIdx.y;
    const int i0   = blockIdx.x * 64;
    const int tid  = threadIdx.x;
    const int w    = tid >> 5;
    const int lane = tid & 31;
    const int col0 = l * 128;

    const float* WhTl = WhT0 + (size_t)l * R * 128 + (size_t)b * 128 * 512;
    const float* srcp = src0 + (size_t)l * R;
    const float* dstp = dst0 + (size_t)l * R;
    const uint32_t* maskb = amask + ((size_t)(b << 9) + i0) * 128;

    for (int k = tid; k < 512; k += 128) dstS[k] = dstp[(b << 9) + k];
    if (tid < 64) srcS[tid] = srcp[(b << 9) + i0 + tid];
    __syncthreads();

    {
        float v = fmaxf(fmaxf(dstS[tid], dstS[tid + 128]),
                        fmaxf(dstS[tid + 256], dstS[tid + 384]));
#pragma unroll
        for (int o = 16; o; o >>= 1) v = fmaxf(v, __shfl_xor_sync(0xffffffffu, v, o));
        if (lane == 0) red[w] = v;
        __syncthreads();
        if (tid == 0) {
            float m = fmaxf(fmaxf(red[0], red[1]), fmaxf(red[2], red[3]));
            mdstS[0] = m;
        }
        __syncthreads();
    }
    const float mdst = mdstS[0];

    for (int k = tid; k < 512; k += 128) {
        float d = dstS[k] - mdst;
        FS2[k] = make_float2(__expf(d), __expf(0.2f * d));
    }
    if (tid < 64) {
        float t2 = srcS[tid] + mdst;
        float m  = fmaxf(t2, 0.2f * t2);
        e1S[tid] = __expf(t2 - m);
        e2S[tid] = __expf(0.2f * t2 - m);
    }
    __syncthreads();

    const int wm = w & 1;
    const int wn = w >> 1;
    const int g  = lane >> 2;
    const int q  = lane & 3;

    const int srow = tid >> 3;
    const int jq   = tid & 7;

    float E1r[4], E2r[4];
#pragma unroll
    for (int qq = 0; qq < 4; ++qq) {
        E1r[qq] = e1S[srow + qq * 16];
        E2r[qq] = e2S[srow + qq * 16];
    }

    float dacc[2][8][4];
#pragma unroll
    for (int mf = 0; mf < 2; ++mf)
#pragma unroll
        for (int nf = 0; nf < 8; ++nf)
#pragma unroll
            for (int c = 0; c < 4; ++c) dacc[mf][nf][c] = 0.f;

    float zl[4] = {0.f, 0.f, 0.f, 0.f};

#pragma unroll
    for (int k = 0; k < 8; ++k) {
        int row = srow + k * 16;
        int so = row * 32 + swz4(row, jq);
        cp16(ws_base + (uint32_t)so * 4, WhTl + (size_t)row * 512 + jq * 4);
    }
    CP_COMMIT();
    {
        const float4* fsp = reinterpret_cast<const float4*>(&FS2[jq * 4]);
        float4 f01 = fsp[0], f23 = fsp[1];
#pragma unroll
        for (int qq = 0; qq < 4; ++qq) {
            int r_ = srow + qq * 16;
            uint32_t mw = maskb[r_ * 128 + jq];
            float E1 = E1r[qq], E2 = E2r[qq];
            float p0 = mask_trunc(fmaxf(E1 * f01.x, E2 * f01.y), __byte_perm(mw, 0, 0x0000));
            float p1 = mask_trunc(fmaxf(E1 * f01.z, E2 * f01.w), __byte_perm(mw, 0, 0x1111));
            float p2 = mask_trunc(fmaxf(E1 * f23.x, E2 * f23.y), __byte_perm(mw, 0, 0x2222));
            float p3 = mask_trunc(fmaxf(E1 * f23.z, E2 * f23.w), __byte_perm(mw, 0, 0x3333));
            zl[qq] += (p0 + p1) + (p2 + p3);
            *reinterpret_cast<float4*>(&PSf[r_ * 32 + swz4(r_, jq)]) =
                make_float4(p0, p1, p2, p3);
        }
    }
    CP_WAIT0();
    __syncthreads();

#pragma unroll 1
    for (int t = 0; t < 16; ++t) {
        const int cur = t & 1, nxt = cur ^ 1;

        if (t < 15) {
            const int tj1 = (t + 1) * 32;
#pragma unroll
            for (int k = 0; k < 8; ++k) {
                int row = srow + k * 16;
                int so = row * 32 + swz4(row, jq);
                cp16(ws_base + (uint32_t)(nxt * WT_F + so) * 4,
                     WhTl + (size_t)row * 512 + tj1 + jq * 4);
            }
            CP_COMMIT();

            const float4* fsp = reinterpret_cast<const float4*>(&FS2[tj1 + jq * 4]);
            float4 f01 = fsp[0], f23 = fsp[1];
            float* PSb = PSf + nxt * PS_F;
            const int wofs = (t + 1) * 8 + jq;
#pragma unroll
            for (int qq = 0; qq < 4; ++qq) {
                int r_ = srow + qq * 16;
                uint32_t mw = maskb[r_ * 128 + wofs];
                float E1 = E1r[qq], E2 = E2r[qq];
                float p0 = mask_trunc(fmaxf(E1 * f01.x, E2 * f01.y), __byte_perm(mw, 0, 0x0000));
                float p1 = mask_trunc(fmaxf(E1 * f01.z, E2 * f01.w), __byte_perm(mw, 0, 0x1111));
                float p2 = mask_trunc(fmaxf(E1 * f23.x, E2 * f23.y), __byte_perm(mw, 0, 0x2222));
                float p3 = mask_trunc(fmaxf(E1 * f23.z, E2 * f23.w), __byte_perm(mw, 0, 0x3333));
                zl[qq] += (p0 + p1) + (p2 + p3);
                *reinterpret_cast<float4*>(&PSb[r_ * 32 + swz4(r_, jq)]) =
                    make_float4(p0, p1, p2, p3);
            }
        }

        const uint32_t* PSu = reinterpret_cast<const uint32_t*>(PSf + cur * PS_F);
        const uint32_t* WSu = reinterpret_cast<const uint32_t*>(WSf + cur * WT_F);
#pragma unroll
        for (int kk = 0; kk < 32; kk += 8) {
            const int k4a = kk >> 2, k4b = (kk >> 2) + 1;
            uint32_t bf0[8], bf1[8];
#pragma unroll
            for (int nf = 0; nf < 8; ++nf) {
                int f = wn * 64 + nf * 8 + g;
                bf0[nf] = WSu[f * 32 + ((k4a ^ g) << 2) + q];
                bf1[nf] = WSu[f * 32 + ((k4b ^ g) << 2) + q];
            }
#pragma unroll
            for (int mf = 0; mf < 2; ++mf) {
                int r_ = wm * 32 + mf * 16 + g;
                uint32_t a0 = PSu[r_ * 32 + ((k4a ^ g) << 2) + q];
                uint32_t a1 = PSu[(r_ + 8) * 32 + ((k4a ^ g) << 2) + q];
                uint32_t a2 = PSu[r_ * 32 + ((k4b ^ g) << 2) + q];
                uint32_t a3 = PSu[(r_ + 8) * 32 + ((k4b ^ g) << 2) + q];
#pragma unroll
                for (int nf = 0; nf < 8; ++nf)
                    mma_tf32(dacc[mf][nf], a0, a1, a2, a3, bf0[nf], bf1[nf]);
            }
        }

        if (t < 15) CP_WAIT0();
        __syncthreads();
    }

    float* zpartS = dyn + WS_OFF;
#pragma unroll
    for (int qq = 0; qq < 4; ++qq) zpartS[(srow + qq * 16) * 8 + jq] = zl[qq];
    __syncthreads();
    if (tid < 64) {
        float z = 0.f;
#pragma unroll
        for (int k = 0; k < 8; ++k) z += zpartS[tid * 8 + k];
        rZS[tid] = 1.f / z;
    }
    __syncthreads();

#pragma unroll
    for (int mf = 0; mf < 2; ++mf) {
#pragma unroll
        for (int h = 0; h < 2; ++h) {
            int rl = wm * 32 + mf * 16 + g + h * 8;
            float rz = rZS[rl];
            float* orow = outp + ((size_t)(b << 9) + i0 + rl) * ld + col0 + wn * 64;
#pragma unroll
            for (int nf = 0; nf < 8; ++nf) {
                float2 v;
                v.x = totf32(elu1(dacc[mf][nf][2 * h]     * rz));
                v.y = totf32(elu1(dacc[mf][nf][2 * h + 1] * rz));
                *reinterpret_cast<float2*>(&orow[nf * 8 + 2 * q]) = v;
            }
        }
    }
}

// ---------------- launch ----------------
extern "C" void kernel_launch(void* const* d_in, const int* in_sizes, int n_in,
                              void* d_out, int out_size)
{
    (void)in_sizes; (void)n_in; (void)out_size;
    const float* compound = (const float*)d_in[0];
    const int*   adj      = (const int*)d_in[1];
    const float* Wst      = (const float*)d_in[2];
    const float* ast      = (const float*)d_in[3];
    const float* Wout     = (const float*)d_in[4];
    const float* aout     = (const float*)d_in[5];
    const float* Wc       = (const float*)d_in[6];
    const float* bc       = (const float*)d_in[7];
    float* out = (float*)d_out;

    float* g_WhT_p;   cudaGetSymbolAddress((void**)&g_WhT_p,  g_WhT);
    float* g_heads_p; cudaGetSymbolAddress((void**)&g_heads_p, g_heads);
    float* g_x_p;     cudaGetSymbolAddress((void**)&g_x_p,    g_x);
    float* g_src_p;   cudaGetSymbolAddress((void**)&g_src_p,  g_src3);
    float* g_dst_p;   cudaGetSymbolAddress((void**)&g_dst_p,  g_dst3);
    uint32_t* g_mask_p; cudaGetSymbolAddress((void**)&g_mask_p, g_adjmask);
    float* g_WoutT_p; cudaGetSymbolAddress((void**)&g_WoutT_p, g_WoutT);
    float* g_WcT_p;   cudaGetSymbolAddress((void**)&g_WcT_p,   g_WcT);

    cudaFuncSetAttribute(k_agg_mma, cudaFuncAttributeMaxDynamicSharedMemorySize,
                         AGG_SMEM_BYTES);
    cudaFuncSetAttribute(k_mma<384, 384, 0>,
                         cudaFuncAttributeMaxDynamicSharedMemorySize, GEMM_SMEM_BYTES);
    cudaFuncSetAttribute(k_mma<128, 128, 1>,
                         cudaFuncAttributeMaxDynamicSharedMemorySize, GEMM_SMEM_BYTES);

    k_pack<<<(R * 128) / 512, 256>>>(adj, g_mask_p);
    k_prepT<<<(128 * 384 + 256 * 128 + 255) / 256, 256>>>(Wout, Wc, g_WoutT_p, g_WcT_p);

    // 3 input-layer projections
    k_proj<34, 34><<<dim3(N / 64, B, 3), 256>>>(
        compound, 34, Wst, ast, g_WhT_p, g_src_p, g_dst_p);

    // 3 head aggregations (64-row CTAs, 4 CTAs/SM)
    k_agg_mma<<<dim3(N / 64, B, 3), 128, AGG_SMEM_BYTES>>>(
        g_mask_p, g_WhT_p, g_src_p, g_dst_p, g_heads_p, 384);

    // out-layer projection (128-row mma GEMM, fused src/dst + WhT store)
    k_mma<384, 384, 0><<<dim3(R / 128, 1), 256, GEMM_SMEM_BYTES>>>(
        g_heads_p, g_WoutT_p, aout,
        g_WhT_p + (size_t)3 * R * 128, g_src_p + (size_t)3 * R, g_dst_p + (size_t)3 * R);

    // out-layer aggregation
    k_agg_mma<<<dim3(N / 64, B, 1), 128, AGG_SMEM_BYTES>>>(
        g_mask_p, g_WhT_p + (size_t)3 * R * 128,
        g_src_p + (size_t)3 * R, g_dst_p + (size_t)3 * R, g_x_p, 128);

    // final dense layer (128-row mma GEMM)
    k_mma<128, 128, 1><<<dim3(R / 128, 2), 256, GEMM_SMEM_BYTES>>>(
        g_x_p, g_WcT_p, bc, out, nullptr, nullptr);
}